// round 9
// baseline (speedup 1.0000x reference)
#include <cuda_runtime.h>
#include <cstdint>

typedef unsigned long long ull;

#define RELK 73728

#define SM_MI     0
#define SM_RELSUM 9600
#define SM_TDUP   18816
#define SM_QKVT   31104
#define SM_WQT    33504
#define SM_LG     35904
#define SM_LB     38208
#define SM_GPART  40512
#define SM_XTS    46656
#define SM_VTR4   46752
#define SM_VTRF   47136
#define SM_XW     47232
#define SM_BQ     47264
#define SM_B2S    47296
#define SM_RED    47392
#define STEP_SMEM_FLOATS 47424
#define STEP_SMEM_BYTES (STEP_SMEM_FLOATS * 4)

__device__ float g_C2[(size_t)8 * 9216 * 64];
__device__ float g_cconst[64];
__device__ float g_relsum0[9216];
__device__ float g_z0[64];
__device__ float g_zbuf[(size_t)2048 * 64];
__device__ float g_relhist[(size_t)16 * 128 * RELK];

__device__ __forceinline__ ull pk2(float x, float y) {
    ull r;
    asm("mov.b64 %0, {%1, %2};" : "=l"(r) : "f"(x), "f"(y));
    return r;
}
__device__ __forceinline__ void fma2(ull& d, ull a, ull b) {
    asm("fma.rn.f32x2 %0, %1, %2, %0;" : "+l"(d) : "l"(a), "l"(b));
}
__device__ __forceinline__ void add2(ull& d, ull a) {
    asm("add.rn.f32x2 %0, %0, %1;" : "+l"(d) : "l"(a));
}
__device__ __forceinline__ void upk2(float& lo, float& hi, ull v) {
    asm("mov.b64 {%0, %1}, %2;" : "=f"(lo), "=f"(hi) : "l"(v));
}

__global__ void __launch_bounds__(256, 1) c2_kernel(const float* __restrict__ Wr,
                                                    const float* __restrict__ W3) {
    __shared__ float Wrs[32 * 96];
    __shared__ float W3s[96 * 64];
    const int tid = threadIdx.x;
    const int de0 = blockIdx.x * 32;
    const int n = blockIdx.y;
    for (int p = tid; p < 3072; p += 256) Wrs[p] = Wr[de0 * 96 + p];
    for (int p = tid; p < 6144; p += 256) W3s[p] = W3[n * 6144 + p];
    __syncthreads();
    const int o = tid & 63, de_b = tid >> 6;
    float acc[8];
#pragma unroll
    for (int i = 0; i < 8; ++i) acc[i] = 0.f;
    for (int r = 0; r < 96; ++r) {
        float bv = W3s[r * 64 + o];
#pragma unroll
        for (int i = 0; i < 8; ++i)
            acc[i] = fmaf(Wrs[(de_b + 4 * i) * 96 + r], bv, acc[i]);
    }
#pragma unroll
    for (int i = 0; i < 8; ++i) {
        int de = de0 + de_b + 4 * i;
        g_C2[((size_t)n * 9216 + de) * 64 + o] = acc[i];
    }
}

__global__ void cconst_kernel(const float* __restrict__ br,
                              const float* __restrict__ W3,
                              const float* __restrict__ b3) {
    int o = threadIdx.x;
    float acc = b3[o];
    for (int nr = 0; nr < 768; ++nr)
        acc = fmaf(br[nr % 96], W3[nr * 64 + o], acc);
    g_cconst[o] = acc;
}

__global__ void relsum0_kernel(const float* __restrict__ rb) {
    int idx = blockIdx.x * 256 + threadIdx.x;
    if (idx < 9216) {
        float s = 0.f;
#pragma unroll
        for (int n = 0; n < 8; ++n) s += rb[n * 9216 + idx];
        g_relsum0[idx] = s;
    }
}

__global__ void zinit_kernel() {
    g_zbuf[(size_t)blockIdx.x * 64 + threadIdx.x] = 0.f;
    if (blockIdx.x == 0) g_z0[threadIdx.x] = 0.f;
}

__global__ void __launch_bounds__(256, 1) z0_kernel(const float* __restrict__ rb) {
    __shared__ float part[256];
    const int o = threadIdx.x & 63, kk = threadIdx.x >> 6;
    const size_t kbase = (size_t)blockIdx.x * 1152;
    float acc = 0.f;
    for (int k = kk; k < 1152; k += 4) {
        size_t kg = kbase + k;
        acc = fmaf(rb[kg], g_C2[kg * 64 + o], acc);
    }
    part[threadIdx.x] = acc;
    __syncthreads();
    if (threadIdx.x < 64) {
        float s = part[o] + part[64 + o] + part[128 + o] + part[192 + o];
        atomicAdd(&g_z0[o], s);
    }
}

__global__ void __launch_bounds__(384, 1) step_kernel(
    const float* __restrict__ x, const float* __restrict__ Wqkv,
    const float* __restrict__ bqkv, const float* __restrict__ ln_g,
    const float* __restrict__ ln_b, const float* __restrict__ pa1,
    const float* __restrict__ pa2, const float* __restrict__ pa3,
    const float* __restrict__ W2, const float* __restrict__ b2,
    const float* __restrict__ item_bias)
{
    extern __shared__ float sm[];
    float* Mi     = sm + SM_MI;
    float* relsum = sm + SM_RELSUM;
    ull*   tdup   = (ull*)(sm + SM_TDUP);
    float* qkvT   = sm + SM_QKVT;
    float* WqT    = sm + SM_WQT;
    float* lg     = sm + SM_LG;
    float* lb     = sm + SM_LB;
    float* Gpart  = sm + SM_GPART;
    float* xts    = sm + SM_XTS;
    float* vtr4   = sm + SM_VTR4;
    float* vtrF   = sm + SM_VTRF;
    float* xw     = sm + SM_XW;
    float* bq     = sm + SM_BQ;
    float* b2s    = sm + SM_B2S;
    float* red    = sm + SM_RED;

    const int tid = threadIdx.x;
    const int b = blockIdx.x;
    const float a1v = *pa1, a2v = *pa2, a3v = *pa3;

    for (int idx = tid; idx < 2304; idx += 384) {
        int f = idx / 24, h = idx % 24;
        WqT[h * 100 + f] = Wqkv[idx];
        lg[idx] = ln_g[idx];
        lb[idx] = ln_b[idx];
    }
    if (tid < 24) bq[tid] = bqkv[tid];
    if (tid < 96) b2s[tid] = b2[tid];
    for (int idx = tid; idx < 9216; idx += 384) {
        Mi[(idx / 96) * 100 + (idx % 96)] = item_bias[idx];
        relsum[idx] = g_relsum0[idx];
    }
    __syncthreads();

    for (int t = 0; t < 16; ++t) {
        if (tid < 96) xts[tid] = x[(t * 128 + b) * 96 + tid];
        __syncthreads();

        for (int idx = tid; idx < 9216; idx += 384) {
            int d = idx / 96, f = idx % 96;
            Mi[d * 100 + f] = fmaf(xts[d], xts[f], Mi[d * 100 + f]);
        }
        __syncthreads();

        {
            int f = tid % 96, q = tid / 96;
            int d0 = q * 24;
            float acc = 0.f;
#pragma unroll 6
            for (int d = d0; d < d0 + 24; ++d)
                acc = fmaf(Mi[d * 100 + f], relsum[d * 96 + f], acc);
            vtr4[q * 96 + f] = acc;
        }
        if (tid < 24) {
            float acc = 0.f;
            for (int f = 0; f < 96; ++f)
                acc = fmaf(xts[f], WqT[tid * 100 + f], acc);
            xw[tid] = acc;
        }
        __syncthreads();
        if (tid < 96)
            vtrF[tid] = vtr4[tid] + vtr4[96 + tid] + vtr4[192 + tid] + vtr4[288 + tid];
        __syncthreads();

        float s1 = 0.f, s2 = 0.f;
        {
            const int dt = tid / 12, ht = tid % 12;
            const int d0 = dt * 3, h0 = ht * 2;
            ull acc2[3][2];
#pragma unroll
            for (int i = 0; i < 3; ++i)
#pragma unroll
                for (int j = 0; j < 2; ++j) acc2[i][j] = 0ull;
#pragma unroll 8
            for (int fp = 0; fp < 48; ++fp) {
                ull m0 = *(const ull*)&Mi[(d0 + 0) * 100 + 2 * fp];
                ull m1 = *(const ull*)&Mi[(d0 + 1) * 100 + 2 * fp];
                ull m2 = *(const ull*)&Mi[(d0 + 2) * 100 + 2 * fp];
                ull w0 = *(const ull*)&WqT[(h0 + 0) * 100 + 2 * fp];
                ull w1 = *(const ull*)&WqT[(h0 + 1) * 100 + 2 * fp];
                fma2(acc2[0][0], m0, w0); fma2(acc2[0][1], m0, w1);
                fma2(acc2[1][0], m1, w0); fma2(acc2[1][1], m1, w1);
                fma2(acc2[2][0], m2, w0); fma2(acc2[2][1], m2, w1);
            }
#pragma unroll
            for (int i = 0; i < 3; ++i)
#pragma unroll
                for (int j = 0; j < 2; ++j) {
                    float lo, hi;
                    upk2(lo, hi, acc2[i][j]);
                    float v = lo + hi + bq[h0 + j] + a2v * vtrF[d0 + i] * xw[h0 + j];
                    qkvT[(h0 + j) * 100 + (d0 + i)] = v;
                    s1 += v;
                    s2 = fmaf(v, v, s2);
                }
        }
#pragma unroll
        for (int o = 16; o > 0; o >>= 1) {
            s1 += __shfl_down_sync(0xffffffffu, s1, o);
            s2 += __shfl_down_sync(0xffffffffu, s2, o);
        }
        if ((tid & 31) == 0) { red[(tid >> 5) * 2] = s1; red[(tid >> 5) * 2 + 1] = s2; }
        __syncthreads();
        if (tid == 0) {
            float S = 0.f, SS = 0.f;
            for (int w = 0; w < 12; ++w) { S += red[w * 2]; SS += red[w * 2 + 1]; }
            float mu = S * (1.f / 2304.f);
            float var = SS * (1.f / 2304.f) - mu * mu;
            red[30] = mu;
            red[31] = rsqrtf(var + 1e-5f);
        }
        __syncthreads();
        const float mu = red[30], rstd = red[31];

        for (int idx = tid; idx < 2304; idx += 384) {
            int h = idx / 96, d = idx % 96;
            float v = qkvT[h * 100 + d];
            qkvT[h * 100 + d] = (v - mu) * rstd * lg[d * 24 + h] + lb[d * 24 + h];
        }
        __syncthreads();

        for (int idx = tid; idx < 6144; idx += 384) {
            int j = idx & 7, d = (idx >> 3) % 96, n = idx / 768;
            float p = qkvT[n * 100 + d] * qkvT[(8 + j) * 100 + d];
            float e = __expf(2.f * p);
            float tv = 1.f - 2.f / (e + 1.f);
            tdup[idx] = pk2(tv, tv);
        }
        __syncthreads();

        {
            const int fp = tid % 48, g = tid / 48;
            const int f0 = 2 * fp;
            ull acc[8];
#pragma unroll
            for (int j = 0; j < 8; ++j) acc[j] = 0ull;
            const float* w2p = W2 + (g * 96) * 96 + f0;
            const ulonglong2* tp = (const ulonglong2*)&tdup[(g * 96) * 8];
#pragma unroll 4
            for (int m = 0; m < 96; ++m) {
                ull w = *(const ull*)&w2p[m * 96];
                ulonglong2 t01 = tp[m * 4 + 0];
                ulonglong2 t23 = tp[m * 4 + 1];
                ulonglong2 t45 = tp[m * 4 + 2];
                ulonglong2 t67 = tp[m * 4 + 3];
                fma2(acc[0], t01.x, w); fma2(acc[1], t01.y, w);
                fma2(acc[2], t23.x, w); fma2(acc[3], t23.y, w);
                fma2(acc[4], t45.x, w); fma2(acc[5], t45.y, w);
                fma2(acc[6], t67.x, w); fma2(acc[7], t67.y, w);
            }
#pragma unroll
            for (int j = 0; j < 8; ++j)
                *(ull*)&Gpart[g * 768 + j * 96 + f0] = acc[j];
        }
        __syncthreads();
        for (int idx = tid; idx < 768; idx += 384) {
            float s = Gpart[idx];
#pragma unroll
            for (int g2 = 1; g2 < 8; ++g2) s += Gpart[g2 * 768 + idx];
            Gpart[idx] = s;
        }
        __syncthreads();

        {
            const int e = tid >> 2, part = tid & 3;
            const int f0b = part * 24;
            ull vp[8];
#pragma unroll
            for (int j = 0; j < 8; ++j) {
                float ve = qkvT[(16 + j) * 100 + e];
                vp[j] = pk2(ve, ve);
            }
#pragma unroll 3
            for (int q = 0; q < 12; ++q) {
                int f0 = f0b + q * 2;
                ull acc = 0ull;
#pragma unroll
                for (int j = 0; j < 8; ++j)
                    fma2(acc, vp[j], *(const ull*)&Gpart[j * 96 + f0]);
                float lo, hi;
                upk2(lo, hi, acc);
                Mi[e * 100 + f0]     = fmaf(a3v, lo + b2s[f0],     Mi[e * 100 + f0]);
                Mi[e * 100 + f0 + 1] = fmaf(a3v, hi + b2s[f0 + 1], Mi[e * 100 + f0 + 1]);
            }
        }

        // op8: R0 only (no rel read); relsum = a1*relsum_old + sum_n R0
        {
            const int ep = tid % 48, g = tid / 48;
            const int e0 = 2 * ep;
            ull vP[8];
#pragma unroll
            for (int j = 0; j < 8; ++j)
                vP[j] = *(const ull*)&qkvT[(16 + j) * 100 + e0];
            float* relo = g_relhist + ((size_t)t * 128 + b) * RELK;
            const ull a1P = pk2(a1v, a1v);
            ull racc[12];
#pragma unroll
            for (int dd = 0; dd < 12; ++dd) racc[dd] = 0ull;
            for (int n = 0; n < 8; ++n) {
#pragma unroll
                for (int dd = 0; dd < 12; ++dd) {
                    int it = n * 96 + g + 8 * dd;
                    const ulonglong2* tp = (const ulonglong2*)&tdup[it * 8];
                    ulonglong2 t01 = tp[0], t23 = tp[1], t45 = tp[2], t67 = tp[3];
                    ull acc = 0ull;
                    fma2(acc, t01.x, vP[0]); fma2(acc, t01.y, vP[1]);
                    fma2(acc, t23.x, vP[2]); fma2(acc, t23.y, vP[3]);
                    fma2(acc, t45.x, vP[4]); fma2(acc, t45.y, vP[5]);
                    fma2(acc, t67.x, vP[6]); fma2(acc, t67.y, vP[7]);
                    *(ull*)&relo[it * 96 + e0] = acc;
                    add2(racc[dd], acc);
                }
            }
#pragma unroll
            for (int dd = 0; dd < 12; ++dd) {
                ull old = *(const ull*)&relsum[(g + 8 * dd) * 96 + e0];
                fma2(racc[dd], a1P, old);
                *(ull*)&relsum[(g + 8 * dd) * 96 + e0] = racc[dd];
            }
        }
        __syncthreads();
    }
}

#define G2_AS_ULL (256 * 34)
#define G2_SMEM_BYTES (G2_AS_ULL * 8 + 32 * 64 * 4)
__global__ void __launch_bounds__(256, 2) out_gemm_kernel() {
    extern __shared__ ull smu[];
    ull* As2 = smu;
    float* Bs = (float*)(smu + G2_AS_ULL);
    const int tid = threadIdx.x;
    const int m0 = blockIdx.x * 256;
    const int k0 = blockIdx.y * 2048;
    const int cg = tid & 7, rg = tid >> 3;
    ull acc[8][4];
#pragma unroll
    for (int i = 0; i < 8; ++i)
#pragma unroll
        for (int j = 0; j < 4; ++j) acc[i][j] = 0ull;

    for (int kc = 0; kc < 2048; kc += 32) {
#pragma unroll
        for (int it = 0; it < 8; ++it) {
            int idx = it * 256 + tid;
            int r = idx >> 3, q = idx & 7;
            float4 v = *(const float4*)&g_relhist[(size_t)(m0 + r) * RELK + k0 + kc + q * 4];
            ulonglong2* dst = (ulonglong2*)&As2[r * 34 + q * 4];
            dst[0] = make_ulonglong2(pk2(v.x, v.x), pk2(v.y, v.y));
            dst[1] = make_ulonglong2(pk2(v.z, v.z), pk2(v.w, v.w));
        }
#pragma unroll
        for (int it = 0; it < 2; ++it) {
            int idx = it * 256 + tid;
            int kr = idx >> 4, q = idx & 15;
            *(float4*)&Bs[kr * 64 + q * 4] =
                *(const float4*)&g_C2[(size_t)(k0 + kc + kr) * 64 + q * 4];
        }
        __syncthreads();
#pragma unroll
        for (int k2 = 0; k2 < 32; k2 += 2) {
            ulonglong2 b00 = *(const ulonglong2*)&Bs[k2 * 64 + cg * 8];
            ulonglong2 b01 = *(const ulonglong2*)&Bs[k2 * 64 + cg * 8 + 4];
            ulonglong2 b10 = *(const ulonglong2*)&Bs[(k2 + 1) * 64 + cg * 8];
            ulonglong2 b11 = *(const ulonglong2*)&Bs[(k2 + 1) * 64 + cg * 8 + 4];
#pragma unroll
            for (int i = 0; i < 8; ++i) {
                ulonglong2 a2k = *(const ulonglong2*)&As2[(rg + 32 * i) * 34 + k2];
                fma2(acc[i][0], a2k.x, b00.x); fma2(acc[i][1], a2k.x, b00.y);
                fma2(acc[i][2], a2k.x, b01.x); fma2(acc[i][3], a2k.x, b01.y);
                fma2(acc[i][0], a2k.y, b10.x); fma2(acc[i][1], a2k.y, b10.y);
                fma2(acc[i][2], a2k.y, b11.x); fma2(acc[i][3], a2k.y, b11.y);
            }
        }
        __syncthreads();
    }
#pragma unroll
    for (int i = 0; i < 8; ++i) {
        int m = m0 + rg + 32 * i;
#pragma unroll
        for (int j = 0; j < 4; ++j) {
            float lo, hi;
            upk2(lo, hi, acc[i][j]);
            atomicAdd(&g_zbuf[(size_t)m * 64 + cg * 8 + 2 * j], lo);
            atomicAdd(&g_zbuf[(size_t)m * 64 + cg * 8 + 2 * j + 1], hi);
        }
    }
}

__global__ void scan_kernel(float* __restrict__ out, const float* __restrict__ pa1) {
    const int b = blockIdx.x;
    const int o = threadIdx.x;
    const float a1v = *pa1;
    const float z0o = g_z0[o], cc = g_cconst[o];
    float acc = 0.f, p = 1.f;
#pragma unroll
    for (int t = 0; t < 16; ++t) {
        p *= a1v;
        acc = fmaf(a1v, acc, g_zbuf[(size_t)(t * 128 + b) * 64 + o]);
        out[(size_t)(t * 128 + b) * 64 + o] = fmaf(p, z0o, acc + cc);
    }
}

extern "C" void kernel_launch(void* const* d_in, const int* in_sizes, int n_in,
                              void* d_out, int out_size) {
    const float* x         = (const float*)d_in[0];
    const float* Wqkv      = (const float*)d_in[1];
    const float* bqkv      = (const float*)d_in[2];
    const float* ln_g      = (const float*)d_in[3];
    const float* ln_b      = (const float*)d_in[4];
    const float* a1        = (const float*)d_in[5];
    const float* a2        = (const float*)d_in[6];
    const float* a3        = (const float*)d_in[7];
    const float* W2        = (const float*)d_in[8];
    const float* b2        = (const float*)d_in[9];
    const float* Wr        = (const float*)d_in[10];
    const float* br        = (const float*)d_in[11];
    const float* W3        = (const float*)d_in[12];
    const float* b3        = (const float*)d_in[13];
    const float* item_bias = (const float*)d_in[14];
    const float* rel_bias  = (const float*)d_in[15];
    float* out = (float*)d_out;

    cudaFuncSetAttribute(step_kernel, cudaFuncAttributeMaxDynamicSharedMemorySize,
                         STEP_SMEM_BYTES);
    cudaFuncSetAttribute(out_gemm_kernel, cudaFuncAttributeMaxDynamicSharedMemorySize,
                         G2_SMEM_BYTES);

    c2_kernel<<<dim3(288, 8), 256>>>(Wr, W3);
    cconst_kernel<<<1, 64>>>(br, W3, b3);
    relsum0_kernel<<<36, 256>>>(rel_bias);
    zinit_kernel<<<2048, 64>>>();
    z0_kernel<<<64, 256>>>(rel_bias);
    step_kernel<<<128, 384, STEP_SMEM_BYTES>>>(x, Wqkv, bqkv, ln_g, ln_b,
                                               a1, a2, a3, W2, b2, item_bias);
    out_gemm_kernel<<<dim3(8, 36), 256, G2_SMEM_BYTES>>>();
    scan_kernel<<<128, 64>>>(out, a1);
}